// round 16
// baseline (speedup 1.0000x reference)
#include <cuda_runtime.h>
#include <cuda_fp16.h>
#include <mma.h>
#include <math.h>

using namespace nvcuda;

#define NN 50000
#define EE 1600000
#define HIN 7
#define HH 128
#define FCC 256
#define CC 2
#define GG 512
#define CAP 128                 // bucket capacity per node (max in-degree ~58)
#define PAD 128                 // row padding for unguarded wmma loads/stores

// ---------------- scratch (device globals; no allocation in launch) ----------
__device__ __align__(16) __half g_hh [(NN+PAD)*HH];    // node features (half, padded)
__device__ __align__(16) __half g_xlh[(NN+PAD)*HH];    // source-transform (half, padded)
__device__ __align__(16) __half g_xrh[(NN+PAD)*HH];    // target-transform (half, padded)
__device__ __align__(16) __half g_Wh [4*HH*HH];        // Wl1,Wr1,Wl2,Wr2 in half
__device__ int   g_deg [NN];                           // per-dst degree / cursor
__device__ int   g_bkt [NN*CAP];                       // bucket CSR: src ids
__device__ float g_pool[GG*HH];
__device__ int   g_cnt[GG];

__device__ __forceinline__ float eluf(float x){ return x > 0.f ? x : (__expf(x) - 1.f); }

// ---------------- init + one-time W->half conversion --------------------------
#define IB 256   // init blocks; conv blocks follow
__global__ void k_init(const float* __restrict__ Wl1, const float* __restrict__ Wr1,
                       const float* __restrict__ Wl2, const float* __restrict__ Wr2) {
    const int bid = blockIdx.x;
    if (bid < IB) {
        int i = bid*256 + threadIdx.x;
        if (i < NN)    g_deg[i]  = 0;
        if (i < GG*HH) g_pool[i] = 0.f;
        if (i < GG)    g_cnt[i]  = 0;
        return;
    }
    // 4 matrices x 4096 float4 = 16384 tasks over 64 blocks x 256 threads
    int tg  = (bid - IB)*256 + threadIdx.x;
    int mat = tg >> 12;
    int idx = tg & 4095;
    const float* src = (mat == 0) ? Wl1 : (mat == 1) ? Wr1 : (mat == 2) ? Wl2 : Wr2;
    float4 w = *((const float4*)src + idx);
    __half2 h0 = __floats2half2_rn(w.x, w.y);
    __half2 h1 = __floats2half2_rn(w.z, w.w);
    uint2 u;
    u.x = *reinterpret_cast<unsigned*>(&h0);
    u.y = *reinterpret_cast<unsigned*>(&h1);
    *((uint2*)(g_Wh + (size_t)mat*HH*HH) + idx) = u;
}

// ---------------- fused: bucket scatter + layer0 linear -----------------------
#define SB ((EE/4 + 255)/256)    // scatter blocks
__global__ __launch_bounds__(256) void k_scat_lin0(const int* __restrict__ ei,
                                                   const float* __restrict__ x,
                                                   const float* __restrict__ Wl, const float* __restrict__ bl,
                                                   const float* __restrict__ Wr, const float* __restrict__ br) {
    if (blockIdx.x < SB) {
        int i = blockIdx.x*256 + threadIdx.x;
        if (i < EE/4) {
            int4 s = ((const int4*)ei)[i];
            int4 d = ((const int4*)(ei + EE))[i];
            g_bkt[(d.x << 7) + atomicAdd(&g_deg[d.x], 1)] = s.x;
            g_bkt[(d.y << 7) + atomicAdd(&g_deg[d.y], 1)] = s.y;
            g_bkt[(d.z << 7) + atomicAdd(&g_deg[d.z], 1)] = s.z;
            g_bkt[(d.w << 7) + atomicAdd(&g_deg[d.w], 1)] = s.w;
        }
        return;
    }
    __shared__ float xs[64*HIN];
    const int bb = blockIdx.x - SB;
    const int n0 = bb * 64;
    const int t  = threadIdx.x;
    for (int i = t; i < 64*HIN; i += 256) {
        int n = n0 + i / HIN;
        xs[i] = (n < NN) ? x[n*HIN + (i % HIN)] : 0.f;
    }
    __syncthreads();
    const int col = t & 127;
    const int grp = t >> 7;
    float wl[HIN], wr[HIN];
#pragma unroll
    for (int k = 0; k < HIN; k++) { wl[k] = Wl[k*HH + col]; wr[k] = Wr[k*HH + col]; }
    float blv = bl[col], brv = br[col];
    for (int nn = 0; nn < 32; nn++) {
        int n = n0 + grp*32 + nn;
        if (n >= NN) break;
        float al = blv, ar = brv;
#pragma unroll
        for (int k = 0; k < HIN; k++) {
            float xv = xs[(grp*32 + nn)*HIN + k];
            al += xv * wl[k];
            ar += xv * wr[k];
        }
        g_xlh[(size_t)n*HH + col] = __float2half_rn(al);
        g_xrh[(size_t)n*HH + col] = __float2half_rn(ar);
    }
}

// ---------------- tensor-core linear: 64x128 / block, 3 CTAs/SM ---------------
// smem: Ws (32KB half, pre-converted W copy) | Bs (8KB float bias tile).
// 8 warps in 4x2: warp = 16 rows x 64 cols (4 acc frags, ~70 regs).
// A fragments direct from g_hh (padded); outputs direct to global (padded).
__global__ __launch_bounds__(256, 3) void k_lin_mma(const float* __restrict__ bl,
                                                    const float* __restrict__ br,
                                                    int layer) {
    extern __shared__ char smem_raw[];
    __half* Ws = (__half*)smem_raw;                    // 128x128 half
    float*  Bs = (float*) (smem_raw + 32768);          // 16x128 float (bias rows)

    const int t   = threadIdx.x;
    const int wid = t >> 5;
    const int row0 = blockIdx.x * 64;
    const bool left = (blockIdx.y == 0);
    const __half* __restrict__ Wh = g_Wh + (size_t)(layer*2 + (left ? 0 : 1))*HH*HH;
    const float* __restrict__ b  = left ? bl : br;
    __half* __restrict__ outh    = left ? g_xlh : g_xrh;

    // copy pre-converted W (2048 uint4) + fill bias tile
#pragma unroll
    for (int i = t; i < 2048; i += 256)
        *((uint4*)Ws + i) = *((const uint4*)Wh + i);
#pragma unroll
    for (int i = t; i < 2048; i += 256) Bs[i] = b[i & 127];
    __syncthreads();

    const int rw = wid >> 1;          // 0..3 -> rows rw*16
    const int cw = (wid & 1) * 64;    // 0 or 64

    wmma::fragment<wmma::accumulator, 16,16,16, float> cfr[4];
#pragma unroll
    for (int j = 0; j < 4; j++)
        wmma::load_matrix_sync(cfr[j], Bs + cw + j*16, 128, wmma::mem_row_major);

    wmma::fragment<wmma::matrix_a, 16,16,16, __half, wmma::row_major> afr;
    wmma::fragment<wmma::matrix_b, 16,16,16, __half, wmma::row_major> bfr;

    const __half* Ag = g_hh + (size_t)(row0 + rw*16)*HH;   // padded: no guard
#pragma unroll
    for (int kb = 0; kb < 8; kb++) {
        wmma::load_matrix_sync(afr, Ag + kb*16, HH);
#pragma unroll
        for (int j = 0; j < 4; j++) {
            wmma::load_matrix_sync(bfr, Ws + (kb*16)*128 + cw + j*16, 128);
            wmma::mma_sync(cfr[j], afr, bfr, cfr[j]);
        }
    }

    // direct global stores (outputs padded; no staging, no sync)
    wmma::fragment<wmma::accumulator, 16,16,16, __half> hfr;
    const size_t row = (size_t)row0 + rw*16;
#pragma unroll
    for (int j = 0; j < 4; j++) {
#pragma unroll
        for (int e = 0; e < 8; e++) hfr.x[e] = __float2half_rn(cfr[j].x[e]);
        wmma::store_matrix_sync(outh + row*HH + cw + j*16, hfr, HH, wmma::mem_row_major);
    }
}

// ---------------- single-edge softmax update (tail path) ----------------------
__device__ __forceinline__ void edge_one(int sn, int lane,
    const uint2* __restrict__ xl2,
    __half2 xr0, __half2 xr1, __half2 at0, __half2 at1, __half2 c02,
    float& m, float& s, __half2& acc0, __half2& acc1) {
    uint2 uu = xl2[(size_t)sn*32 + lane];
    __half2 v0 = *reinterpret_cast<__half2*>(&uu.x);
    __half2 v1 = *reinterpret_cast<__half2*>(&uu.y);
    __half2 t0 = __hadd2(v0, xr0), t1 = __hadd2(v1, xr1);
    t0 = __hmax2(t0, __hmul2(t0, c02));
    t1 = __hmax2(t1, __hmul2(t1, c02));
    __half2 pq = __hmul2(at0, t0); pq = __hfma2(at1, t1, pq);
    float q = __low2float(pq) + __high2float(pq);
#pragma unroll
    for (int o = 16; o > 0; o >>= 1) q += __shfl_xor_sync(0xffffffffu, q, o);
    if (q > m) {
        float r = __expf(m - q); m = q;
        s = s*r + 1.0f;
        __half2 r2 = __float2half2_rn(r);
        acc0 = __hfma2(acc0, r2, v0);
        acc1 = __hfma2(acc1, r2, v1);
    } else {
        float w = __expf(q - m); s += w;
        __half2 w2 = __float2half2_rn(w);
        acc0 = __hfma2(w2, v0, acc0);
        acc1 = __hfma2(w2, v1, acc1);
    }
}

// ---------------- fused edge attention (+ optional mean-pool) -----------------
template <bool POOL>
__global__ __launch_bounds__(256) void k_edge(const float* __restrict__ att,
                                              const float* __restrict__ bo,
                                              const int* __restrict__ batch) {
    const int gw   = (blockIdx.x * 256 + threadIdx.x) >> 5;
    const int lane = threadIdx.x & 31;
    if (gw >= NN) return;
    const int dst = gw;

    const uint2* __restrict__ xl2 = (const uint2*)g_xlh;
    const uint2* __restrict__ xr2 = (const uint2*)g_xrh;

    float4 a4 = *(const float4*)(att + lane*4);
    const __half2 at0 = __floats2half2_rn(a4.x, a4.y);
    const __half2 at1 = __floats2half2_rn(a4.z, a4.w);
    const __half2 c02 = __float2half2_rn(0.2f);

    uint2 xru = xr2[(size_t)dst*32 + lane];
    const __half2 xr0 = *reinterpret_cast<__half2*>(&xru.x);
    const __half2 xr1 = *reinterpret_cast<__half2*>(&xru.y);

    uint2 xdu = xl2[(size_t)dst*32 + lane];
    const __half2 xd0 = *reinterpret_cast<__half2*>(&xdu.x);
    const __half2 xd1 = *reinterpret_cast<__half2*>(&xdu.y);

    __half2 u0 = __hadd2(xd0, xr0), u1 = __hadd2(xd1, xr1);
    u0 = __hmax2(u0, __hmul2(u0, c02));
    u1 = __hmax2(u1, __hmul2(u1, c02));
    __half2 pp = __hmul2(at0, u0); pp = __hfma2(at1, u1, pp);
    float pf = __low2float(pp) + __high2float(pp);
#pragma unroll
    for (int o = 16; o > 0; o >>= 1) pf += __shfl_xor_sync(0xffffffffu, pf, o);

    float m = pf, s = 1.0f;
    __half2 acc0 = xd0, acc1 = xd1;

    const int beg = dst << 7;
    const int end = beg + g_deg[dst];
    int j = beg;

    int4 sn = (j + 4 <= end) ? *(const int4*)(g_bkt + j) : make_int4(0,0,0,0);
    while (j + 4 <= end) {
        const int4 cur = sn;
        uint2 uA = xl2[(size_t)cur.x*32 + lane];
        uint2 uB = xl2[(size_t)cur.y*32 + lane];
        uint2 uC = xl2[(size_t)cur.z*32 + lane];
        uint2 uD = xl2[(size_t)cur.w*32 + lane];
        j += 4;
        if (j + 4 <= end) sn = *(const int4*)(g_bkt + j);

        __half2 vA0 = *reinterpret_cast<__half2*>(&uA.x), vA1 = *reinterpret_cast<__half2*>(&uA.y);
        __half2 vB0 = *reinterpret_cast<__half2*>(&uB.x), vB1 = *reinterpret_cast<__half2*>(&uB.y);
        __half2 vC0 = *reinterpret_cast<__half2*>(&uC.x), vC1 = *reinterpret_cast<__half2*>(&uC.y);
        __half2 vD0 = *reinterpret_cast<__half2*>(&uD.x), vD1 = *reinterpret_cast<__half2*>(&uD.y);

        __half2 tA0 = __hadd2(vA0, xr0), tA1 = __hadd2(vA1, xr1);
        __half2 tB0 = __hadd2(vB0, xr0), tB1 = __hadd2(vB1, xr1);
        __half2 tC0 = __hadd2(vC0, xr0), tC1 = __hadd2(vC1, xr1);
        __half2 tD0 = __hadd2(vD0, xr0), tD1 = __hadd2(vD1, xr1);
        tA0 = __hmax2(tA0, __hmul2(tA0, c02)); tA1 = __hmax2(tA1, __hmul2(tA1, c02));
        tB0 = __hmax2(tB0, __hmul2(tB0, c02)); tB1 = __hmax2(tB1, __hmul2(tB1, c02));
        tC0 = __hmax2(tC0, __hmul2(tC0, c02)); tC1 = __hmax2(tC1, __hmul2(tC1, c02));
        tD0 = __hmax2(tD0, __hmul2(tD0, c02)); tD1 = __hmax2(tD1, __hmul2(tD1, c02));
        __half2 pA = __hmul2(at0, tA0); pA = __hfma2(at1, tA1, pA);
        __half2 pB = __hmul2(at0, tB0); pB = __hfma2(at1, tB1, pB);
        __half2 pC = __hmul2(at0, tC0); pC = __hfma2(at1, tC1, pC);
        __half2 pD = __hmul2(at0, tD0); pD = __hfma2(at1, tD1, pD);

        __half2 qp0 = __hadd2(__halves2half2(__low2half(pA), __low2half(pB)),
                              __halves2half2(__high2half(pA), __high2half(pB)));
        __half2 qp1 = __hadd2(__halves2half2(__low2half(pC), __low2half(pD)),
                              __halves2half2(__high2half(pC), __high2half(pD)));
#pragma unroll
        for (int o = 16; o > 0; o >>= 1) {
            unsigned x0 = __shfl_xor_sync(0xffffffffu, *reinterpret_cast<unsigned*>(&qp0), o);
            unsigned x1 = __shfl_xor_sync(0xffffffffu, *reinterpret_cast<unsigned*>(&qp1), o);
            qp0 = __hadd2(qp0, *reinterpret_cast<__half2*>(&x0));
            qp1 = __hadd2(qp1, *reinterpret_cast<__half2*>(&x1));
        }
        float2 qf0 = __half22float2(qp0);
        float2 qf1 = __half22float2(qp1);

        float mloc = fmaxf(fmaxf(qf0.x, qf0.y), fmaxf(qf1.x, qf1.y));
        if (mloc > m) {
            float r = __expf(m - mloc);
            s *= r; m = mloc;
            __half2 r2 = __float2half2_rn(r);
            acc0 = __hmul2(acc0, r2);
            acc1 = __hmul2(acc1, r2);
        }
        float w0 = __expf(qf0.x - m), w1 = __expf(qf0.y - m);
        float w2 = __expf(qf1.x - m), w3 = __expf(qf1.y - m);
        s += (w0 + w1) + (w2 + w3);
        __half2 h0 = __float2half2_rn(w0), h1 = __float2half2_rn(w1);
        __half2 h2 = __float2half2_rn(w2), h3 = __float2half2_rn(w3);
        acc0 = __hfma2(h0, vA0, acc0); acc1 = __hfma2(h0, vA1, acc1);
        acc0 = __hfma2(h1, vB0, acc0); acc1 = __hfma2(h1, vB1, acc1);
        acc0 = __hfma2(h2, vC0, acc0); acc1 = __hfma2(h2, vC1, acc1);
        acc0 = __hfma2(h3, vD0, acc0); acc1 = __hfma2(h3, vD1, acc1);
    }

    while (j < end) {
        edge_one(g_bkt[j], lane, xl2, xr0, xr1, at0, at1, c02, m, s, acc0, acc1);
        j++;
    }

    const float inv = 1.0f / s;
    float4 b4 = *(const float4*)(bo + lane*4);
    float2 f0 = __half22float2(acc0);
    float2 f1 = __half22float2(acc1);
    float ox = eluf(f0.x*inv + b4.x), oy = eluf(f0.y*inv + b4.y);
    float oz = eluf(f1.x*inv + b4.z), ow = eluf(f1.y*inv + b4.w);

    if (POOL) {
        int g = batch[dst];
        atomicAdd(&g_pool[g*HH + lane*4 + 0], ox);
        atomicAdd(&g_pool[g*HH + lane*4 + 1], oy);
        atomicAdd(&g_pool[g*HH + lane*4 + 2], oz);
        atomicAdd(&g_pool[g*HH + lane*4 + 3], ow);
        if (lane == 0) atomicAdd(&g_cnt[g], 1);
    } else {
        __half2 o0 = __floats2half2_rn(ox, oy);
        __half2 o1 = __floats2half2_rn(oz, ow);
        uint2 u;
        u.x = *reinterpret_cast<unsigned*>(&o0);
        u.y = *reinterpret_cast<unsigned*>(&o1);
        ((uint2*)g_hh)[(size_t)dst*32 + lane] = u;
    }
}

// ---------------- MLP head + log_softmax -------------------------------------
__global__ __launch_bounds__(128) void k_head(const float* __restrict__ fc1W, const float* __restrict__ fc1b,
                                              const float* __restrict__ fc2W, const float* __restrict__ fc2b,
                                              float* __restrict__ out) {
    __shared__ float gs[HH];
    __shared__ float red0[128], red1[128];
    const int gid = blockIdx.x;
    const int t = threadIdx.x;
    float c = (float)g_cnt[gid];
    if (c < 1.f) c = 1.f;
    gs[t] = g_pool[gid*HH + t] / c;
    __syncthreads();
    float p0 = 0.f, p1 = 0.f;
    for (int cc = t; cc < FCC; cc += 128) {
        float z = fc1b[cc];
        for (int k = 0; k < HH; k++) z += gs[k] * fc1W[k*FCC + cc];
        z = fmaxf(z, 0.f);
        p0 += z * fc2W[cc*CC + 0];
        p1 += z * fc2W[cc*CC + 1];
    }
    red0[t] = p0; red1[t] = p1;
    __syncthreads();
    for (int st = 64; st > 0; st >>= 1) {
        if (t < st) { red0[t] += red0[t + st]; red1[t] += red1[t + st]; }
        __syncthreads();
    }
    if (t == 0) {
        float l0 = red0[0] + fc2b[0];
        float l1 = red1[0] + fc2b[1];
        float mm  = fmaxf(l0, l1);
        float lse = mm + logf(__expf(l0 - mm) + __expf(l1 - mm));
        out[gid*CC + 0] = l0 - lse;
        out[gid*CC + 1] = l1 - lse;
    }
}

// ---------------- launch ------------------------------------------------------
extern "C" void kernel_launch(void* const* d_in, const int* in_sizes, int n_in,
                              void* d_out, int out_size) {
    const float* x     = (const float*)d_in[0];
    const int*   ei    = (const int*)  d_in[1];
    const int*   batch = (const int*)  d_in[2];
    const float* Wl0 = (const float*)d_in[3];  const float* bl0 = (const float*)d_in[4];
    const float* Wr0 = (const float*)d_in[5];  const float* br0 = (const float*)d_in[6];
    const float* at0 = (const float*)d_in[7];  const float* bo0 = (const float*)d_in[8];
    const float* Wl1 = (const float*)d_in[9];  const float* bl1 = (const float*)d_in[10];
    const float* Wr1 = (const float*)d_in[11]; const float* br1 = (const float*)d_in[12];
    const float* at1 = (const float*)d_in[13]; const float* bo1 = (const float*)d_in[14];
    const float* Wl2 = (const float*)d_in[15]; const float* bl2 = (const float*)d_in[16];
    const float* Wr2 = (const float*)d_in[17]; const float* br2 = (const float*)d_in[18];
    const float* at2 = (const float*)d_in[19]; const float* bo2 = (const float*)d_in[20];
    const float* fc1W = (const float*)d_in[21]; const float* fc1b = (const float*)d_in[22];
    const float* fc2W = (const float*)d_in[23]; const float* fc2b = (const float*)d_in[24];
    float* out = (float*)d_out;

    const int SMEM_LIN = 32768 + 8192;   // 40 KB dynamic
    cudaFuncSetAttribute(k_lin_mma, cudaFuncAttributeMaxDynamicSharedMemorySize, SMEM_LIN);

    dim3 ling((NN + 63)/64, 2);
    const int L0B = (NN + 63)/64;

    k_init     <<<IB + 64, 256>>>(Wl1, Wr1, Wl2, Wr2);
    k_scat_lin0<<<SB + L0B, 256>>>(ei, x, Wl0, bl0, Wr0, br0);

    k_edge<false><<<(NN + 7)/8, 256>>>(at0, bo0, nullptr);

    k_lin_mma<<<ling, 256, SMEM_LIN>>>(bl1, br1, 0);
    k_edge<false><<<(NN + 7)/8, 256>>>(at1, bo1, nullptr);

    k_lin_mma<<<ling, 256, SMEM_LIN>>>(bl2, br2, 1);
    k_edge<true><<<(NN + 7)/8, 256>>>(at2, bo2, batch);   // fused mean-pool

    k_head<<<GG, 128>>>(fc1W, fc1b, fc2W, fc2b, out);
}

// round 17
// speedup vs baseline: 1.1345x; 1.1345x over previous
#include <cuda_runtime.h>
#include <cuda_fp16.h>
#include <mma.h>
#include <math.h>

using namespace nvcuda;

#define NN 50000
#define EE 1600000
#define HIN 7
#define HH 128
#define FCC 256
#define CC 2
#define GG 512
#define CAP 128                 // bucket capacity per node (max in-degree ~58)
#define PAD 128                 // row padding for unguarded wmma loads/stores

// ---------------- scratch (device globals; no allocation in launch) ----------
__device__ __align__(16) __half g_hh [(NN+PAD)*HH];    // node features (half, padded)
__device__ __align__(16) __half g_xlh[(NN+PAD)*HH];    // source-transform (half, padded)
__device__ __align__(16) __half g_xrh[(NN+PAD)*HH];    // target-transform (half, padded)
__device__ __align__(16) __half g_Wh [4*HH*HH];        // Wl1,Wr1,Wl2,Wr2 in half
__device__ __align__(16) float  g_bias[4*16*HH];       // bias rows (16x128 each)
__device__ int   g_deg [NN];                           // per-dst degree / cursor
__device__ int   g_bkt [NN*CAP];                       // bucket CSR: src ids
__device__ float g_pool[GG*HH];
__device__ int   g_cnt[GG];

__device__ __forceinline__ float eluf(float x){ return x > 0.f ? x : (__expf(x) - 1.f); }

// ---------------- init + one-time W->half + bias expansion --------------------
#define IB 256   // init blocks; conv blocks follow; then bias blocks
__global__ void k_init(const float* __restrict__ Wl1, const float* __restrict__ Wr1,
                       const float* __restrict__ Wl2, const float* __restrict__ Wr2,
                       const float* __restrict__ bl1, const float* __restrict__ br1,
                       const float* __restrict__ bl2, const float* __restrict__ br2) {
    const int bid = blockIdx.x;
    if (bid < IB) {
        int i = bid*256 + threadIdx.x;
        if (i < NN)    g_deg[i]  = 0;
        if (i < GG*HH) g_pool[i] = 0.f;
        if (i < GG)    g_cnt[i]  = 0;
        return;
    }
    if (bid < IB + 64) {
        // 4 matrices x 4096 float4 = 16384 tasks over 64 blocks x 256 threads
        int tg  = (bid - IB)*256 + threadIdx.x;
        int mat = tg >> 12;
        int idx = tg & 4095;
        const float* src = (mat == 0) ? Wl1 : (mat == 1) ? Wr1 : (mat == 2) ? Wl2 : Wr2;
        float4 w = *((const float4*)src + idx);
        __half2 h0 = __floats2half2_rn(w.x, w.y);
        __half2 h1 = __floats2half2_rn(w.z, w.w);
        uint2 u;
        u.x = *reinterpret_cast<unsigned*>(&h0);
        u.y = *reinterpret_cast<unsigned*>(&h1);
        *((uint2*)(g_Wh + (size_t)mat*HH*HH) + idx) = u;
        return;
    }
    // bias expansion: 4 vectors -> 16x128 tiles; 4*2048 = 8192 tasks / 32 blocks
    int tg  = (bid - IB - 64)*256 + threadIdx.x;
    int vec = tg >> 11;       // 0..3
    int idx = tg & 2047;      // 16*128
    const float* src = (vec == 0) ? bl1 : (vec == 1) ? br1 : (vec == 2) ? bl2 : br2;
    g_bias[(size_t)vec*2048 + idx] = src[idx & 127];
}

// ---------------- fused: bucket scatter + layer0 linear -----------------------
#define SB ((EE/4 + 255)/256)    // scatter blocks
__global__ __launch_bounds__(256) void k_scat_lin0(const int* __restrict__ ei,
                                                   const float* __restrict__ x,
                                                   const float* __restrict__ Wl, const float* __restrict__ bl,
                                                   const float* __restrict__ Wr, const float* __restrict__ br) {
    if (blockIdx.x < SB) {
        int i = blockIdx.x*256 + threadIdx.x;
        if (i < EE/4) {
            int4 s = ((const int4*)ei)[i];
            int4 d = ((const int4*)(ei + EE))[i];
            g_bkt[(d.x << 7) + atomicAdd(&g_deg[d.x], 1)] = s.x;
            g_bkt[(d.y << 7) + atomicAdd(&g_deg[d.y], 1)] = s.y;
            g_bkt[(d.z << 7) + atomicAdd(&g_deg[d.z], 1)] = s.z;
            g_bkt[(d.w << 7) + atomicAdd(&g_deg[d.w], 1)] = s.w;
        }
        return;
    }
    __shared__ float xs[64*HIN];
    const int bb = blockIdx.x - SB;
    const int n0 = bb * 64;
    const int t  = threadIdx.x;
    for (int i = t; i < 64*HIN; i += 256) {
        int n = n0 + i / HIN;
        xs[i] = (n < NN) ? x[n*HIN + (i % HIN)] : 0.f;
    }
    __syncthreads();
    const int col = t & 127;
    const int grp = t >> 7;
    float wl[HIN], wr[HIN];
#pragma unroll
    for (int k = 0; k < HIN; k++) { wl[k] = Wl[k*HH + col]; wr[k] = Wr[k*HH + col]; }
    float blv = bl[col], brv = br[col];
    for (int nn = 0; nn < 32; nn++) {
        int n = n0 + grp*32 + nn;
        if (n >= NN) break;
        float al = blv, ar = brv;
#pragma unroll
        for (int k = 0; k < HIN; k++) {
            float xv = xs[(grp*32 + nn)*HIN + k];
            al += xv * wl[k];
            ar += xv * wr[k];
        }
        g_xlh[(size_t)n*HH + col] = __float2half_rn(al);
        g_xrh[(size_t)n*HH + col] = __float2half_rn(ar);
    }
}

// ---------------- tensor-core linear: ZERO smem, all L1 -----------------------
// 4 warps in 2x2: warp = 32 rows x 64 cols (8 acc frags). Block = 64x128.
// A frags from g_hh, B frags from g_Wh (L1-resident), bias init from g_bias.
// No prologue, no syncthreads. launch_bounds(128,4) -> 4 CTAs/SM on regs.
__global__ __launch_bounds__(128, 4) void k_lin_mma(int layer) {
    const int wid = threadIdx.x >> 5;
    const int row0 = blockIdx.x * 64;
    const bool left = (blockIdx.y == 0);
    const int sel = layer*2 + (left ? 0 : 1);
    const __half* __restrict__ Wh = g_Wh   + (size_t)sel*HH*HH;
    const float*  __restrict__ Bt = g_bias + (size_t)sel*2048;
    __half* __restrict__ outh     = left ? g_xlh : g_xrh;

    const int rw = wid >> 1;          // 0..1 -> rows rw*32
    const int cw = (wid & 1) * 64;    // 0 or 64

    wmma::fragment<wmma::accumulator, 16,16,16, float> cfr[8];  // [rt*4+j]
#pragma unroll
    for (int j = 0; j < 4; j++) {
        wmma::load_matrix_sync(cfr[j],   Bt + cw + j*16, HH, wmma::mem_row_major);
        wmma::load_matrix_sync(cfr[4+j], Bt + cw + j*16, HH, wmma::mem_row_major);
    }

    wmma::fragment<wmma::matrix_a, 16,16,16, __half, wmma::row_major> afr0, afr1;
    wmma::fragment<wmma::matrix_b, 16,16,16, __half, wmma::row_major> bfr;

    const __half* Ag = g_hh + (size_t)(row0 + rw*32)*HH;   // padded: no guard
#pragma unroll
    for (int kb = 0; kb < 8; kb++) {
        wmma::load_matrix_sync(afr0, Ag + kb*16,          HH);
        wmma::load_matrix_sync(afr1, Ag + 16*HH + kb*16,  HH);
#pragma unroll
        for (int j = 0; j < 4; j++) {
            wmma::load_matrix_sync(bfr, Wh + (kb*16)*HH + cw + j*16, HH);
            wmma::mma_sync(cfr[j],   afr0, bfr, cfr[j]);
            wmma::mma_sync(cfr[4+j], afr1, bfr, cfr[4+j]);
        }
    }

    // direct global stores (outputs padded)
    wmma::fragment<wmma::accumulator, 16,16,16, __half> hfr;
#pragma unroll
    for (int rt = 0; rt < 2; rt++) {
#pragma unroll
        for (int j = 0; j < 4; j++) {
#pragma unroll
            for (int e = 0; e < 8; e++) hfr.x[e] = __float2half_rn(cfr[rt*4+j].x[e]);
            size_t row = (size_t)row0 + rw*32 + rt*16;
            wmma::store_matrix_sync(outh + row*HH + cw + j*16, hfr, HH, wmma::mem_row_major);
        }
    }
}

// ---------------- single-edge softmax update (tail path) ----------------------
__device__ __forceinline__ void edge_one(int sn, int lane,
    const uint2* __restrict__ xl2,
    __half2 xr0, __half2 xr1, __half2 at0, __half2 at1, __half2 c02,
    float& m, float& s, __half2& acc0, __half2& acc1) {
    uint2 uu = xl2[(size_t)sn*32 + lane];
    __half2 v0 = *reinterpret_cast<__half2*>(&uu.x);
    __half2 v1 = *reinterpret_cast<__half2*>(&uu.y);
    __half2 t0 = __hadd2(v0, xr0), t1 = __hadd2(v1, xr1);
    t0 = __hmax2(t0, __hmul2(t0, c02));
    t1 = __hmax2(t1, __hmul2(t1, c02));
    __half2 pq = __hmul2(at0, t0); pq = __hfma2(at1, t1, pq);
    float q = __low2float(pq) + __high2float(pq);
#pragma unroll
    for (int o = 16; o > 0; o >>= 1) q += __shfl_xor_sync(0xffffffffu, q, o);
    if (q > m) {
        float r = __expf(m - q); m = q;
        s = s*r + 1.0f;
        __half2 r2 = __float2half2_rn(r);
        acc0 = __hfma2(acc0, r2, v0);
        acc1 = __hfma2(acc1, r2, v1);
    } else {
        float w = __expf(q - m); s += w;
        __half2 w2 = __float2half2_rn(w);
        acc0 = __hfma2(w2, v0, acc0);
        acc1 = __hfma2(w2, v1, acc1);
    }
}

// ---------------- fused edge attention (+ optional mean-pool) -----------------
template <bool POOL>
__global__ __launch_bounds__(256) void k_edge(const float* __restrict__ att,
                                              const float* __restrict__ bo,
                                              const int* __restrict__ batch) {
    const int gw   = (blockIdx.x * 256 + threadIdx.x) >> 5;
    const int lane = threadIdx.x & 31;
    if (gw >= NN) return;
    const int dst = gw;

    const uint2* __restrict__ xl2 = (const uint2*)g_xlh;
    const uint2* __restrict__ xr2 = (const uint2*)g_xrh;

    float4 a4 = *(const float4*)(att + lane*4);
    const __half2 at0 = __floats2half2_rn(a4.x, a4.y);
    const __half2 at1 = __floats2half2_rn(a4.z, a4.w);
    const __half2 c02 = __float2half2_rn(0.2f);

    uint2 xru = xr2[(size_t)dst*32 + lane];
    const __half2 xr0 = *reinterpret_cast<__half2*>(&xru.x);
    const __half2 xr1 = *reinterpret_cast<__half2*>(&xru.y);

    uint2 xdu = xl2[(size_t)dst*32 + lane];
    const __half2 xd0 = *reinterpret_cast<__half2*>(&xdu.x);
    const __half2 xd1 = *reinterpret_cast<__half2*>(&xdu.y);

    __half2 u0 = __hadd2(xd0, xr0), u1 = __hadd2(xd1, xr1);
    u0 = __hmax2(u0, __hmul2(u0, c02));
    u1 = __hmax2(u1, __hmul2(u1, c02));
    __half2 pp = __hmul2(at0, u0); pp = __hfma2(at1, u1, pp);
    float pf = __low2float(pp) + __high2float(pp);
#pragma unroll
    for (int o = 16; o > 0; o >>= 1) pf += __shfl_xor_sync(0xffffffffu, pf, o);

    float m = pf, s = 1.0f;
    __half2 acc0 = xd0, acc1 = xd1;

    const int beg = dst << 7;
    const int end = beg + g_deg[dst];
    int j = beg;

    int4 sn = (j + 4 <= end) ? *(const int4*)(g_bkt + j) : make_int4(0,0,0,0);
    while (j + 4 <= end) {
        const int4 cur = sn;
        uint2 uA = xl2[(size_t)cur.x*32 + lane];
        uint2 uB = xl2[(size_t)cur.y*32 + lane];
        uint2 uC = xl2[(size_t)cur.z*32 + lane];
        uint2 uD = xl2[(size_t)cur.w*32 + lane];
        j += 4;
        if (j + 4 <= end) sn = *(const int4*)(g_bkt + j);

        __half2 vA0 = *reinterpret_cast<__half2*>(&uA.x), vA1 = *reinterpret_cast<__half2*>(&uA.y);
        __half2 vB0 = *reinterpret_cast<__half2*>(&uB.x), vB1 = *reinterpret_cast<__half2*>(&uB.y);
        __half2 vC0 = *reinterpret_cast<__half2*>(&uC.x), vC1 = *reinterpret_cast<__half2*>(&uC.y);
        __half2 vD0 = *reinterpret_cast<__half2*>(&uD.x), vD1 = *reinterpret_cast<__half2*>(&uD.y);

        __half2 tA0 = __hadd2(vA0, xr0), tA1 = __hadd2(vA1, xr1);
        __half2 tB0 = __hadd2(vB0, xr0), tB1 = __hadd2(vB1, xr1);
        __half2 tC0 = __hadd2(vC0, xr0), tC1 = __hadd2(vC1, xr1);
        __half2 tD0 = __hadd2(vD0, xr0), tD1 = __hadd2(vD1, xr1);
        tA0 = __hmax2(tA0, __hmul2(tA0, c02)); tA1 = __hmax2(tA1, __hmul2(tA1, c02));
        tB0 = __hmax2(tB0, __hmul2(tB0, c02)); tB1 = __hmax2(tB1, __hmul2(tB1, c02));
        tC0 = __hmax2(tC0, __hmul2(tC0, c02)); tC1 = __hmax2(tC1, __hmul2(tC1, c02));
        tD0 = __hmax2(tD0, __hmul2(tD0, c02)); tD1 = __hmax2(tD1, __hmul2(tD1, c02));
        __half2 pA = __hmul2(at0, tA0); pA = __hfma2(at1, tA1, pA);
        __half2 pB = __hmul2(at0, tB0); pB = __hfma2(at1, tB1, pB);
        __half2 pC = __hmul2(at0, tC0); pC = __hfma2(at1, tC1, pC);
        __half2 pD = __hmul2(at0, tD0); pD = __hfma2(at1, tD1, pD);

        __half2 qp0 = __hadd2(__halves2half2(__low2half(pA), __low2half(pB)),
                              __halves2half2(__high2half(pA), __high2half(pB)));
        __half2 qp1 = __hadd2(__halves2half2(__low2half(pC), __low2half(pD)),
                              __halves2half2(__high2half(pC), __high2half(pD)));
#pragma unroll
        for (int o = 16; o > 0; o >>= 1) {
            unsigned x0 = __shfl_xor_sync(0xffffffffu, *reinterpret_cast<unsigned*>(&qp0), o);
            unsigned x1 = __shfl_xor_sync(0xffffffffu, *reinterpret_cast<unsigned*>(&qp1), o);
            qp0 = __hadd2(qp0, *reinterpret_cast<__half2*>(&x0));
            qp1 = __hadd2(qp1, *reinterpret_cast<__half2*>(&x1));
        }
        float2 qf0 = __half22float2(qp0);
        float2 qf1 = __half22float2(qp1);

        float mloc = fmaxf(fmaxf(qf0.x, qf0.y), fmaxf(qf1.x, qf1.y));
        if (mloc > m) {
            float r = __expf(m - mloc);
            s *= r; m = mloc;
            __half2 r2 = __float2half2_rn(r);
            acc0 = __hmul2(acc0, r2);
            acc1 = __hmul2(acc1, r2);
        }
        float w0 = __expf(qf0.x - m), w1 = __expf(qf0.y - m);
        float w2 = __expf(qf1.x - m), w3 = __expf(qf1.y - m);
        s += (w0 + w1) + (w2 + w3);
        __half2 h0 = __float2half2_rn(w0), h1 = __float2half2_rn(w1);
        __half2 h2 = __float2half2_rn(w2), h3 = __float2half2_rn(w3);
        acc0 = __hfma2(h0, vA0, acc0); acc1 = __hfma2(h0, vA1, acc1);
        acc0 = __hfma2(h1, vB0, acc0); acc1 = __hfma2(h1, vB1, acc1);
        acc0 = __hfma2(h2, vC0, acc0); acc1 = __hfma2(h2, vC1, acc1);
        acc0 = __hfma2(h3, vD0, acc0); acc1 = __hfma2(h3, vD1, acc1);
    }

    while (j < end) {
        edge_one(g_bkt[j], lane, xl2, xr0, xr1, at0, at1, c02, m, s, acc0, acc1);
        j++;
    }

    const float inv = 1.0f / s;
    float4 b4 = *(const float4*)(bo + lane*4);
    float2 f0 = __half22float2(acc0);
    float2 f1 = __half22float2(acc1);
    float ox = eluf(f0.x*inv + b4.x), oy = eluf(f0.y*inv + b4.y);
    float oz = eluf(f1.x*inv + b4.z), ow = eluf(f1.y*inv + b4.w);

    if (POOL) {
        int g = batch[dst];
        atomicAdd(&g_pool[g*HH + lane*4 + 0], ox);
        atomicAdd(&g_pool[g*HH + lane*4 + 1], oy);
        atomicAdd(&g_pool[g*HH + lane*4 + 2], oz);
        atomicAdd(&g_pool[g*HH + lane*4 + 3], ow);
        if (lane == 0) atomicAdd(&g_cnt[g], 1);
    } else {
        __half2 o0 = __floats2half2_rn(ox, oy);
        __half2 o1 = __floats2half2_rn(oz, ow);
        uint2 u;
        u.x = *reinterpret_cast<unsigned*>(&o0);
        u.y = *reinterpret_cast<unsigned*>(&o1);
        ((uint2*)g_hh)[(size_t)dst*32 + lane] = u;
    }
}

// ---------------- MLP head + log_softmax -------------------------------------
__global__ __launch_bounds__(128) void k_head(const float* __restrict__ fc1W, const float* __restrict__ fc1b,
                                              const float* __restrict__ fc2W, const float* __restrict__ fc2b,
                                              float* __restrict__ out) {
    __shared__ float gs[HH];
    __shared__ float red0[128], red1[128];
    const int gid = blockIdx.x;
    const int t = threadIdx.x;
    float c = (float)g_cnt[gid];
    if (c < 1.f) c = 1.f;
    gs[t] = g_pool[gid*HH + t] / c;
    __syncthreads();
    float p0 = 0.f, p1 = 0.f;
    for (int cc = t; cc < FCC; cc += 128) {
        float z = fc1b[cc];
        for (int k = 0; k < HH; k++) z += gs[k] * fc1W[k*FCC + cc];
        z = fmaxf(z, 0.f);
        p0 += z * fc2W[cc*CC + 0];
        p1 += z * fc2W[cc*CC + 1];
    }
    red0[t] = p0; red1[t] = p1;
    __syncthreads();
    for (int st = 64; st > 0; st >>= 1) {
        if (t < st) { red0[t] += red0[t + st]; red1[t] += red1[t + st]; }
        __syncthreads();
    }
    if (t == 0) {
        float l0 = red0[0] + fc2b[0];
        float l1 = red1[0] + fc2b[1];
        float mm  = fmaxf(l0, l1);
        float lse = mm + logf(__expf(l0 - mm) + __expf(l1 - mm));
        out[gid*CC + 0] = l0 - lse;
        out[gid*CC + 1] = l1 - lse;
    }
}

// ---------------- launch ------------------------------------------------------
extern "C" void kernel_launch(void* const* d_in, const int* in_sizes, int n_in,
                              void* d_out, int out_size) {
    const float* x     = (const float*)d_in[0];
    const int*   ei    = (const int*)  d_in[1];
    const int*   batch = (const int*)  d_in[2];
    const float* Wl0 = (const float*)d_in[3];  const float* bl0 = (const float*)d_in[4];
    const float* Wr0 = (const float*)d_in[5];  const float* br0 = (const float*)d_in[6];
    const float* at0 = (const float*)d_in[7];  const float* bo0 = (const float*)d_in[8];
    const float* Wl1 = (const float*)d_in[9];  const float* bl1 = (const float*)d_in[10];
    const float* Wr1 = (const float*)d_in[11]; const float* br1 = (const float*)d_in[12];
    const float* at1 = (const float*)d_in[13]; const float* bo1 = (const float*)d_in[14];
    const float* Wl2 = (const float*)d_in[15]; const float* bl2 = (const float*)d_in[16];
    const float* Wr2 = (const float*)d_in[17]; const float* br2 = (const float*)d_in[18];
    const float* at2 = (const float*)d_in[19]; const float* bo2 = (const float*)d_in[20];
    const float* fc1W = (const float*)d_in[21]; const float* fc1b = (const float*)d_in[22];
    const float* fc2W = (const float*)d_in[23]; const float* fc2b = (const float*)d_in[24];
    float* out = (float*)d_out;

    dim3 ling((NN + 63)/64, 2);
    const int L0B = (NN + 63)/64;

    k_init     <<<IB + 64 + 32, 256>>>(Wl1, Wr1, Wl2, Wr2, bl1, br1, bl2, br2);
    k_scat_lin0<<<SB + L0B, 256>>>(ei, x, Wl0, bl0, Wr0, br0);

    k_edge<false><<<(NN + 7)/8, 256>>>(at0, bo0, nullptr);

    k_lin_mma<<<ling, 128>>>(0);
    k_edge<false><<<(NN + 7)/8, 256>>>(at1, bo1, nullptr);

    k_lin_mma<<<ling, 128>>>(1);
    k_edge<true><<<(NN + 7)/8, 256>>>(at2, bo2, batch);   // fused mean-pool

    k_head<<<GG, 128>>>(fc1W, fc1b, fc2W, fc2b, out);
}